// round 1
// baseline (speedup 1.0000x reference)
#include <cuda_runtime.h>
#include <cuda_bf16.h>

// Problem constants
static constexpr int BATCH = 8;
static constexpr int SEQ   = 2048;
static constexpr int DIM   = 768;
static constexpr long long BSD = (long long)BATCH * SEQ * DIM;   // 12,582,912
static constexpr long long BSS = (long long)BATCH * SEQ * SEQ;   // 33,554,432

// Scratch (device globals: allocation-free per harness rules)
__device__ float g_qkv[3 * BATCH * SEQ * DIM];  // [q | k | v], each [B,S,D]
__device__ float g_s[BATCH * SEQ * SEQ];        // scores / attn  [B,S,S]

// ---------------------------------------------------------------------------
// Tiled fp32 GEMM: C = alpha * A @ B(^T)
//   A: [M,K] row-major (per-batch stride sA)
//   B: NN -> [K,N] row-major ; NT -> [N,K] row-major (stride sB)
//   C: [M,N] row-major (stride sC)
// All of M,N divisible by 128; K divisible by 16. No bounds checks.
// ---------------------------------------------------------------------------
#define BM 128
#define BN 128
#define BKD 16
#define TM 8
#define TN 8

template <bool BT>
__global__ __launch_bounds__(256, 2) void gemm128(
    const float* __restrict__ Ab, const float* __restrict__ Bb,
    float* __restrict__ Cb,
    int M, int N, int K,
    long long sA, long long sB, long long sC, float alpha)
{
    const float* A = Ab + (long long)blockIdx.z * sA;
    const float* B = Bb + (long long)blockIdx.z * sB;
    float*       C = Cb + (long long)blockIdx.z * sC;

    __shared__ float As[BKD][BM + 4];
    __shared__ float Bs[BKD][BN + 4];

    const int tid = threadIdx.x;
    const int tx  = tid & 15;   // 0..15 -> N direction
    const int ty  = tid >> 4;   // 0..15 -> M direction
    const int row0 = blockIdx.y * BM;
    const int col0 = blockIdx.x * BN;

    float acc[TM][TN];
#pragma unroll
    for (int i = 0; i < TM; i++)
#pragma unroll
        for (int j = 0; j < TN; j++) acc[i][j] = 0.f;

    // A-style (transposing) loader indices: 64 rows x 16 cols per pass
    const int aRow = tid >> 2;          // 0..63
    const int aCol = (tid & 3) * 4;     // 0,4,8,12
    // B NN loader indices: 8 rows x 128 cols per pass
    const int bRow = tid >> 5;          // 0..7
    const int bCol = (tid & 31) * 4;    // 0..124

    for (int kt = 0; kt < K; kt += BKD) {
        // --- A tile: [BM x BK] transposed into As[k][m] ---
#pragma unroll
        for (int it = 0; it < 2; it++) {
            int r = aRow + it * 64;
            float4 v = *(const float4*)(A + (long long)(row0 + r) * K + kt + aCol);
            As[aCol + 0][r] = v.x;
            As[aCol + 1][r] = v.y;
            As[aCol + 2][r] = v.z;
            As[aCol + 3][r] = v.w;
        }
        if (BT) {
            // --- B tile (NT): B is [N,K]; load [BN x BK] transposed into Bs[k][n] ---
#pragma unroll
            for (int it = 0; it < 2; it++) {
                int r = aRow + it * 64;
                float4 v = *(const float4*)(B + (long long)(col0 + r) * K + kt + aCol);
                Bs[aCol + 0][r] = v.x;
                Bs[aCol + 1][r] = v.y;
                Bs[aCol + 2][r] = v.z;
                Bs[aCol + 3][r] = v.w;
            }
        } else {
            // --- B tile (NN): B is [K,N]; load [BK x BN] directly ---
#pragma unroll
            for (int it = 0; it < 2; it++) {
                int r = bRow + it * 8;
                float4 v = *(const float4*)(B + (long long)(kt + r) * N + col0 + bCol);
                *(float4*)&Bs[r][bCol] = v;
            }
        }
        __syncthreads();

#pragma unroll
        for (int k = 0; k < BKD; k++) {
            float a[TM], b[TN];
#pragma unroll
            for (int i = 0; i < TM; i += 4)
                *(float4*)&a[i] = *(const float4*)&As[k][ty * TM + i];
#pragma unroll
            for (int j = 0; j < TN; j += 4)
                *(float4*)&b[j] = *(const float4*)&Bs[k][tx * TN + j];
#pragma unroll
            for (int i = 0; i < TM; i++)
#pragma unroll
                for (int j = 0; j < TN; j++)
                    acc[i][j] = fmaf(a[i], b[j], acc[i][j]);
        }
        __syncthreads();
    }

#pragma unroll
    for (int i = 0; i < TM; i++) {
        long long cr = (long long)(row0 + ty * TM + i) * N + col0 + tx * TN;
#pragma unroll
        for (int j = 0; j < TN; j += 4) {
            float4 v;
            v.x = acc[i][j + 0] * alpha;
            v.y = acc[i][j + 1] * alpha;
            v.z = acc[i][j + 2] * alpha;
            v.w = acc[i][j + 3] * alpha;
            *(float4*)(C + cr + j) = v;
        }
    }
}

// ---------------------------------------------------------------------------
// Row softmax over 2048 columns: 1 block of 256 threads per row, 8 elems/thread
// ---------------------------------------------------------------------------
__global__ __launch_bounds__(256) void softmax2048(float* __restrict__ S)
{
    float* row = S + (long long)blockIdx.x * SEQ;
    const int tid = threadIdx.x;

    float x[8];
#pragma unroll
    for (int i = 0; i < 8; i++) x[i] = row[i * 256 + tid];

    // max
    float m = x[0];
#pragma unroll
    for (int i = 1; i < 8; i++) m = fmaxf(m, x[i]);
#pragma unroll
    for (int o = 16; o > 0; o >>= 1)
        m = fmaxf(m, __shfl_xor_sync(0xffffffffu, m, o));

    __shared__ float red[8];
    if ((tid & 31) == 0) red[tid >> 5] = m;
    __syncthreads();
    float mAll = red[0];
#pragma unroll
    for (int i = 1; i < 8; i++) mAll = fmaxf(mAll, red[i]);
    __syncthreads();

    // exp + sum
    float s = 0.f;
#pragma unroll
    for (int i = 0; i < 8; i++) {
        x[i] = __expf(x[i] - mAll);
        s += x[i];
    }
#pragma unroll
    for (int o = 16; o > 0; o >>= 1)
        s += __shfl_xor_sync(0xffffffffu, s, o);
    if ((tid & 31) == 0) red[tid >> 5] = s;
    __syncthreads();
    float tot = 0.f;
#pragma unroll
    for (int i = 0; i < 8; i++) tot += red[i];

    const float inv = 1.f / tot;
#pragma unroll
    for (int i = 0; i < 8; i++) row[i * 256 + tid] = x[i] * inv;
}

// ---------------------------------------------------------------------------
// Launch
// ---------------------------------------------------------------------------
extern "C" void kernel_launch(void* const* d_in, const int* in_sizes, int n_in,
                              void* d_out, int out_size)
{
    const float* x = (const float*)d_in[0];   // [8, 2048, 768]
    const float* w = (const float*)d_in[1];   // [3, 768, 768]
    float* out     = (float*)d_out;           // [8, 2048, 768]

    float* qkv = nullptr;
    float* sc  = nullptr;
    cudaGetSymbolAddress((void**)&qkv, g_qkv);
    cudaGetSymbolAddress((void**)&sc,  g_s);

    const float INV_SCALE = 0.125f;  // 1 / sqrt(64)

    // 1) QKV projection: [16384,768] @ [768,768] for each of the 3 weights
    //    A stride 0 (shared x), B stride D*D, C stride BSD (q|k|v segments)
    {
        dim3 grid(DIM / BN, (BATCH * SEQ) / BM, 3);
        gemm128<false><<<grid, 256>>>(x, w, qkv,
                                      BATCH * SEQ, DIM, DIM,
                                      0LL, (long long)DIM * DIM, BSD, 1.0f);
    }

    // 2) scores = Q @ K^T / 8  (batched over 8)
    {
        dim3 grid(SEQ / BN, SEQ / BM, BATCH);
        gemm128<true><<<grid, 256>>>(qkv /*Q*/, qkv + BSD /*K*/, sc,
                                     SEQ, SEQ, DIM,
                                     (long long)SEQ * DIM, (long long)SEQ * DIM,
                                     (long long)SEQ * SEQ, INV_SCALE);
    }

    // 3) softmax over last dim (16384 rows of 2048)
    softmax2048<<<BATCH * SEQ, 256>>>(sc);

    // 4) out = attn @ V  (batched over 8)
    {
        dim3 grid(DIM / BN, SEQ / BM, BATCH);
        gemm128<false><<<grid, 256>>>(sc, qkv + 2 * BSD /*V*/, out,
                                      SEQ, DIM, SEQ,
                                      (long long)SEQ * SEQ, (long long)SEQ * DIM,
                                      (long long)SEQ * DIM, 1.0f);
    }
}

// round 2
// speedup vs baseline: 2.9790x; 2.9790x over previous
#include <cuda_runtime.h>
#include <cuda_bf16.h>
#include <cstdint>

// Problem constants
static constexpr int BATCH = 8;
static constexpr int SEQ   = 2048;
static constexpr int DIM   = 768;
static constexpr long long BSD = (long long)BATCH * SEQ * DIM;

// Scratch (device globals: allocation-free per harness rules)
__device__ float g_qkv[3 * BATCH * SEQ * DIM];  // [q | k | v], each [B,S,D]
__device__ float g_s[BATCH * SEQ * SEQ];        // scores / attn  [B,S,S]

__device__ __forceinline__ uint32_t f2tf32(float f) {
    uint32_t u;
    asm volatile("cvt.rna.tf32.f32 %0, %1;" : "=r"(u) : "f"(f));
    return u;
}

__device__ __forceinline__ void mma_tf32(
    float& c0, float& c1, float& c2, float& c3,
    uint32_t a0, uint32_t a1, uint32_t a2, uint32_t a3,
    uint32_t b0, uint32_t b1)
{
    asm volatile(
        "mma.sync.aligned.m16n8k8.row.col.f32.tf32.tf32.f32 "
        "{%0,%1,%2,%3}, {%4,%5,%6,%7}, {%8,%9}, {%0,%1,%2,%3};\n"
        : "+f"(c0), "+f"(c1), "+f"(c2), "+f"(c3)
        : "r"(a0), "r"(a1), "r"(a2), "r"(a3), "r"(b0), "r"(b1));
}

// ---------------------------------------------------------------------------
// Tensor-core tf32 GEMM: C = alpha * A @ B(^T)
//   A: [M,K] row-major (per-batch stride sA)
//   B: NN (BT=false) -> [K,N] row-major ; NT (BT=true) -> [N,K] row-major
//   C: [M,N] row-major
// M,N divisible by 128; K divisible by 32. No bounds checks.
//
// CTA tile 128x128x32, 8 warps (2x4), warp tile 64x32, mma m16n8k8.
// Smem layouts (tf32 bits as uint32):
//   As  [m][k]  stride 36  -> frag LDS bank = (4*gid + tig) % 32, conflict-free
//   BsNN[k][n]  stride 136 -> frag LDS bank = (8*tig + gid) % 32, conflict-free
//   BsNT[n][k]  stride 36  -> same as As
// ---------------------------------------------------------------------------
#define BM 128
#define BN 128
#define BK 32

template <bool BT>
__global__ __launch_bounds__(256) void mma_gemm(
    const float* __restrict__ Ab, const float* __restrict__ Bb,
    float* __restrict__ Cb,
    int M, int N, int K,
    long long sA, long long sB, long long sC, float alpha)
{
    const float* A = Ab + (long long)blockIdx.z * sA;
    const float* B = Bb + (long long)blockIdx.z * sB;
    float*       C = Cb + (long long)blockIdx.z * sC;

    constexpr int AS_STRIDE = BK + 4;             // 36
    constexpr int BS_STRIDE = BT ? (BK + 4) : (BN + 8);  // 36 or 136
    __shared__ uint32_t As[BM * AS_STRIDE];
    __shared__ uint32_t Bs[BT ? (BN * (BK + 4)) : (BK * (BN + 8))];

    const int tid  = threadIdx.x;
    const int warp = tid >> 5;
    const int lane = tid & 31;
    const int gid  = lane >> 2;   // 0..7
    const int tig  = lane & 3;    // 0..3
    const int wm   = (warp >> 2) * 64;   // warp m offset (0 or 64)
    const int wn   = (warp & 3) * 32;    // warp n offset (0,32,64,96)
    const int row0 = blockIdx.y * BM;
    const int col0 = blockIdx.x * BN;

    float c[4][4][4];
#pragma unroll
    for (int i = 0; i < 4; i++)
#pragma unroll
        for (int j = 0; j < 4; j++)
#pragma unroll
            for (int r = 0; r < 4; r++) c[i][j][r] = 0.f;

    // A loader: float4 along k; row = tid>>3 (+32 per pass), col4 = (tid&7)*4
    const int aR = tid >> 3;
    const int aC = (tid & 7) * 4;
    // B NN loader: float4 along n; k = tid>>5 (+8 per pass), n4 = (tid&31)*4
    const int bR = tid >> 5;
    const int bC = (tid & 31) * 4;

    for (int kt = 0; kt < K; kt += BK) {
        // ---- A tile [BM x BK] -> As[m][k] (direct copy, cvt to tf32) ----
#pragma unroll
        for (int p = 0; p < 4; p++) {
            int r = aR + p * 32;
            float4 v = *(const float4*)(A + (long long)(row0 + r) * K + kt + aC);
            uint4 u = make_uint4(f2tf32(v.x), f2tf32(v.y), f2tf32(v.z), f2tf32(v.w));
            *(uint4*)&As[r * AS_STRIDE + aC] = u;
        }
        if (BT) {
            // ---- B tile (NT): B[N,K] -> Bs[n][k] (direct copy) ----
#pragma unroll
            for (int p = 0; p < 4; p++) {
                int r = aR + p * 32;
                float4 v = *(const float4*)(B + (long long)(col0 + r) * K + kt + aC);
                uint4 u = make_uint4(f2tf32(v.x), f2tf32(v.y), f2tf32(v.z), f2tf32(v.w));
                *(uint4*)&Bs[r * BS_STRIDE + aC] = u;
            }
        } else {
            // ---- B tile (NN): B[K,N] -> Bs[k][n] (direct copy) ----
#pragma unroll
            for (int p = 0; p < 4; p++) {
                int r = bR + p * 8;
                float4 v = *(const float4*)(B + (long long)(kt + r) * N + col0 + bC);
                uint4 u = make_uint4(f2tf32(v.x), f2tf32(v.y), f2tf32(v.z), f2tf32(v.w));
                *(uint4*)&Bs[r * BS_STRIDE + bC] = u;
            }
        }
        __syncthreads();

#pragma unroll
        for (int ks = 0; ks < BK; ks += 8) {
            // A fragments: 4 m-tiles
            uint32_t a[4][4];
#pragma unroll
            for (int i = 0; i < 4; i++) {
                int m = wm + 16 * i + gid;
                a[i][0] = As[m * AS_STRIDE + ks + tig];
                a[i][1] = As[(m + 8) * AS_STRIDE + ks + tig];
                a[i][2] = As[m * AS_STRIDE + ks + tig + 4];
                a[i][3] = As[(m + 8) * AS_STRIDE + ks + tig + 4];
            }
            // B fragments: 4 n-tiles
            uint32_t b[4][2];
#pragma unroll
            for (int j = 0; j < 4; j++) {
                int n = wn + 8 * j + gid;
                if (BT) {
                    b[j][0] = Bs[n * BS_STRIDE + ks + tig];
                    b[j][1] = Bs[n * BS_STRIDE + ks + tig + 4];
                } else {
                    b[j][0] = Bs[(ks + tig) * BS_STRIDE + n];
                    b[j][1] = Bs[(ks + tig + 4) * BS_STRIDE + n];
                }
            }
#pragma unroll
            for (int i = 0; i < 4; i++)
#pragma unroll
                for (int j = 0; j < 4; j++)
                    mma_tf32(c[i][j][0], c[i][j][1], c[i][j][2], c[i][j][3],
                             a[i][0], a[i][1], a[i][2], a[i][3],
                             b[j][0], b[j][1]);
        }
        __syncthreads();
    }

    // Epilogue: c0,c1 -> (row, col..col+1); c2,c3 -> (row+8, ...)
#pragma unroll
    for (int i = 0; i < 4; i++) {
        int rowA = row0 + wm + 16 * i + gid;
#pragma unroll
        for (int j = 0; j < 4; j++) {
            int col = col0 + wn + 8 * j + 2 * tig;
            float2 v0 = make_float2(c[i][j][0] * alpha, c[i][j][1] * alpha);
            float2 v1 = make_float2(c[i][j][2] * alpha, c[i][j][3] * alpha);
            *(float2*)(C + (long long)rowA * N + col) = v0;
            *(float2*)(C + (long long)(rowA + 8) * N + col) = v1;
        }
    }
}

// ---------------------------------------------------------------------------
// Row softmax over 2048 columns: 1 block of 256 threads per row
// ---------------------------------------------------------------------------
__global__ __launch_bounds__(256) void softmax2048(float* __restrict__ S)
{
    float* row = S + (long long)blockIdx.x * SEQ;
    const int tid = threadIdx.x;

    float x[8];
#pragma unroll
    for (int i = 0; i < 8; i++) x[i] = row[i * 256 + tid];

    float m = x[0];
#pragma unroll
    for (int i = 1; i < 8; i++) m = fmaxf(m, x[i]);
#pragma unroll
    for (int o = 16; o > 0; o >>= 1)
        m = fmaxf(m, __shfl_xor_sync(0xffffffffu, m, o));

    __shared__ float red[8];
    if ((tid & 31) == 0) red[tid >> 5] = m;
    __syncthreads();
    float mAll = red[0];
#pragma unroll
    for (int i = 1; i < 8; i++) mAll = fmaxf(mAll, red[i]);
    __syncthreads();

    float s = 0.f;
#pragma unroll
    for (int i = 0; i < 8; i++) {
        x[i] = __expf(x[i] - mAll);
        s += x[i];
    }
#pragma unroll
    for (int o = 16; o > 0; o >>= 1)
        s += __shfl_xor_sync(0xffffffffu, s, o);
    if ((tid & 31) == 0) red[tid >> 5] = s;
    __syncthreads();
    float tot = 0.f;
#pragma unroll
    for (int i = 0; i < 8; i++) tot += red[i];

    const float inv = 1.f / tot;
#pragma unroll
    for (int i = 0; i < 8; i++) row[i * 256 + tid] = x[i] * inv;
}

// ---------------------------------------------------------------------------
// Launch
// ---------------------------------------------------------------------------
extern "C" void kernel_launch(void* const* d_in, const int* in_sizes, int n_in,
                              void* d_out, int out_size)
{
    const float* x = (const float*)d_in[0];   // [8, 2048, 768]
    const float* w = (const float*)d_in[1];   // [3, 768, 768]
    float* out     = (float*)d_out;           // [8, 2048, 768]

    float* qkv = nullptr;
    float* sc  = nullptr;
    cudaGetSymbolAddress((void**)&qkv, g_qkv);
    cudaGetSymbolAddress((void**)&sc,  g_s);

    const float INV_SCALE = 0.125f;  // 1 / sqrt(64)

    // 1) QKV projection: [16384,768] @ [768,768] per weight slice (z=3)
    {
        dim3 grid(DIM / BN, (BATCH * SEQ) / BM, 3);
        mma_gemm<false><<<grid, 256>>>(x, w, qkv,
                                       BATCH * SEQ, DIM, DIM,
                                       0LL, (long long)DIM * DIM, BSD, 1.0f);
    }

    // 2) scores = Q @ K^T / 8  (batched over 8)
    {
        dim3 grid(SEQ / BN, SEQ / BM, BATCH);
        mma_gemm<true><<<grid, 256>>>(qkv /*Q*/, qkv + BSD /*K*/, sc,
                                      SEQ, SEQ, DIM,
                                      (long long)SEQ * DIM, (long long)SEQ * DIM,
                                      (long long)SEQ * SEQ, INV_SCALE);
    }

    // 3) softmax over last dim (16384 rows of 2048)
    softmax2048<<<BATCH * SEQ, 256>>>(sc);

    // 4) out = attn @ V  (batched over 8)
    {
        dim3 grid(DIM / BN, SEQ / BM, BATCH);
        mma_gemm<false><<<grid, 256>>>(sc, qkv + 2 * BSD /*V*/, out,
                                       SEQ, DIM, SEQ,
                                       (long long)SEQ * SEQ, (long long)SEQ * DIM,
                                       (long long)SEQ * DIM, 1.0f);
    }
}